// round 6
// baseline (speedup 1.0000x reference)
#include <cuda_runtime.h>
#include <cuda_fp16.h>
#include <math.h>
#include <stdint.h>

#define BB 8
#define CC 256
#define NN 2048

// rn-scaled 2-way fp16 splits, K-contiguous: g_xs[b][n][s*256 + c], s in {0,1}
__device__ __align__(16) __half g_xs[(size_t)BB * NN * 512];
// transposed f32 copy for fuse gathers: g_xt[b][n][c]
__device__ __align__(16) float g_xt[(size_t)BB * NN * CC];
__device__ int g_idx[BB * NN];

// ---------------------------------------------------------------------------
// prep: per token compute rn, write f32 transpose (g_xt) and rn-scaled 2-way
// fp16 splits (g_xs). grid (NN/32, BB), 256 threads.
// ---------------------------------------------------------------------------
__global__ __launch_bounds__(256) void prep_kernel(const float* __restrict__ x) {
    __shared__ __half S[32][520];
    __shared__ float nsum[32][8];
    __shared__ float rns[32];
    int b = blockIdx.y, n0 = blockIdx.x * 32;
    int tid = threadIdx.x, nl = tid & 31, c8 = tid >> 5;
    const float* xp = x + (size_t)b * CC * NN + n0 + nl;

    float v[32];
    float s = 0.f;
#pragma unroll
    for (int cc = 0; cc < 32; ++cc) {
        int c = c8 * 32 + cc;
        v[cc] = xp[(size_t)c * NN];
        s = fmaf(v[cc], v[cc], s);
    }
    nsum[nl][c8] = s;
    __syncthreads();
    if (tid < 32) {
        float t = 0.f;
#pragma unroll
        for (int q = 0; q < 8; ++q) t += nsum[tid][q];
        rns[tid] = rsqrtf(t + (float)CC * 1e-6f);
    }
    __syncthreads();
    float rn = rns[nl];

    float* xt = g_xt + ((size_t)(b * NN + n0 + nl)) * 256 + c8 * 32;
#pragma unroll
    for (int q = 0; q < 8; ++q)
        *(float4*)(xt + q * 4) = make_float4(v[q * 4], v[q * 4 + 1], v[q * 4 + 2], v[q * 4 + 3]);

#pragma unroll
    for (int cc = 0; cc < 32; ++cc) {
        int c = c8 * 32 + cc;
        float f = v[cc] * rn;
        __half h1 = __float2half_rn(f);
        float r1 = f - __half2float(h1);
        __half h2 = __float2half_rn(r1);
        S[nl][c] = h1; S[nl][256 + c] = h2;
    }
    __syncthreads();

    __half* outb = g_xs + ((size_t)(b * NN + n0)) * 512;
#pragma unroll
    for (int r = 0; r < 8; ++r) {
        int idx = tid + r * 256;
        int row = idx >> 6, c16 = idx & 63;
        uint4 val = *(const uint4*)&S[row][c16 * 8];
        *(uint4*)(outb + (size_t)row * 512 + c16 * 8) = val;
    }
}

// ---------------------------------------------------------------------------
// smem map for simargmax (byte offsets; 16B chunk granularity)
// ---------------------------------------------------------------------------
#define ARES_BYTES (2 * 128 * 33 * 16)          // resident A splits 0,1; padded stride 33 chunks
#define BOFF       (ARES_BYTES)                 // 135168
#define BSLOT      (256 * 9 * 16)               // 36864: one 256-row B tile, padded stride 9
#define MVOFF      (BOFF + 2 * BSLOT)           // 208896
#define MJOFF      (MVOFF + 3 * 512)
#define SMEM_TOTAL (MJOFF + 3 * 512)            // 211968

__device__ __forceinline__ void ldsm4(uint32_t* r, uint32_t saddr) {
    asm volatile("ldmatrix.sync.aligned.m8n8.x4.shared.b16 {%0,%1,%2,%3}, [%4];"
                 : "=r"(r[0]), "=r"(r[1]), "=r"(r[2]), "=r"(r[3]) : "r"(saddr));
}
__device__ __forceinline__ void mma16816(float (&d)[4], const uint32_t (&a)[4],
                                         uint32_t b0, uint32_t b1) {
    asm volatile(
        "mma.sync.aligned.m16n8k16.row.col.f32.f16.f16.f32 "
        "{%0,%1,%2,%3},{%4,%5,%6,%7},{%8,%9},{%0,%1,%2,%3};"
        : "+f"(d[0]), "+f"(d[1]), "+f"(d[2]), "+f"(d[3])
        : "r"(a[0]), "r"(a[1]), "r"(a[2]), "r"(a[3]), "r"(b0), "r"(b1));
}

// async copy of one 256x64-half B tile (sb,kc) into ring slot
__device__ __forceinline__ void cpB(uint32_t smb, const __half* xsb,
                                    int j0, int sb, int kc, int slot, int tid) {
#pragma unroll
    for (int q = 0; q < 4; ++q) {
        int idx = tid + q * 512;
        int row = idx >> 3, ch = idx & 7;
        uint32_t sa = smb + BOFF + slot * BSLOT + ((row * 9 + ch) << 4);
        const void* ga = xsb + (size_t)(j0 + row) * 512 + sb * 256 + kc * 64 + ch * 8;
        asm volatile("cp.async.cg.shared.global [%0], [%1], 16;" :: "r"(sa), "l"(ga));
    }
    asm volatile("cp.async.commit_group;" ::: "memory");
}

// ---------------------------------------------------------------------------
// simargmax: emulated-fp32 GEMM via 3 fp16 split pairs {(0,0),(1,0),(0,1)}
// + fused argmax. grid (16, BB), 512 threads = 16 warps (4 M x 4 N).
// CTA tile 128 x 256.
// ---------------------------------------------------------------------------
__global__ __launch_bounds__(512, 1) void simargmax_kernel() {
    extern __shared__ __align__(1024) char sm[];
    const int b = blockIdx.y, i0 = blockIdx.x * 128;
    const int tid = threadIdx.x, lane = tid & 31, wid = tid >> 5;
    const int wm = wid >> 2, wn = wid & 3;
    const uint32_t smb = (uint32_t)__cvta_generic_to_shared(sm);
    const __half* xsb = g_xs + (size_t)b * NN * 512;

    // resident A: both splits, rows i0..i0+127, full K=256 (32 chunks/row)
#pragma unroll
    for (int r = 0; r < 16; ++r) {
        int idx = tid + r * 512;            // 8192 chunks
        int s   = idx >> 12;
        int row = (idx >> 5) & 127;
        int ch  = idx & 31;
        uint4 v = *(const uint4*)(xsb + (size_t)(i0 + row) * 512 + s * 256 + ch * 8);
        *(uint4*)(sm + ((((s << 7) + row) * 33 + ch) << 4)) = v;
    }

    const int ar0 = wm * 32 + (lane & 15);          // A ldmatrix row (+ mt*16)
    const int akh = lane >> 4;                      // A k-half chunk
    const int jr0 = wn * 64 + ((lane >> 4) & 1) * 8 + (lane & 7);  // B row (+ ntp*16)
    const int bkh = (lane >> 3) & 1;                // B k-half chunk

    const float NEG = __int_as_float(0xff800000);
    float best[4]; int bidx[4];
#pragma unroll
    for (int s = 0; s < 4; ++s) { best[s] = NEG; bidx[s] = 0; }

    __syncthreads();   // A resident visible to all warps

    for (int jt = 0; jt < 8; ++jt) {
        const int j0 = jt * 256;
        float acc[2][8][4];
#pragma unroll
        for (int mt = 0; mt < 2; ++mt)
#pragma unroll
            for (int nt = 0; nt < 8; ++nt)
#pragma unroll
                for (int rr = 0; rr < 4; ++rr) acc[mt][nt][rr] = 0.f;

        cpB(smb, xsb, j0, 0, 0, 0, tid);     // tile 0 -> slot 0

        // 8 B tiles per jt: it = sb*4 + kc. sb=0 pairs with A splits {0,1};
        // sb=1 pairs with A split {0} only.
        for (int it = 0; it < 8; ++it) {
            const int buf = it & 1;
            const int kc = it & 3;
            const int nq = (it < 4) ? 2 : 1;
            const int itn = it + 1;
            if (itn < 8) {
                cpB(smb, xsb, j0, itn >> 2, itn & 3, itn & 1, tid);
                asm volatile("cp.async.wait_group 1;" ::: "memory");
            } else {
                asm volatile("cp.async.wait_group 0;" ::: "memory");
            }
            __syncthreads();    // tile 'it' visible to all

#pragma unroll
            for (int ks = 0; ks < 4; ++ks) {
                uint32_t bf[4][4];
#pragma unroll
                for (int ntp = 0; ntp < 4; ++ntp) {
                    uint32_t bd = smb + BOFF + buf * BSLOT +
                        ((((jr0 + ntp * 16) * 9) + ks * 2 + bkh) << 4);
                    ldsm4(bf[ntp], bd);
                }
                for (int q = 0; q < nq; ++q) {
                    uint32_t a[2][4];
                    const int cb = kc * 8 + ks * 2;
#pragma unroll
                    for (int mt = 0; mt < 2; ++mt) {
                        uint32_t ad = smb + (((((q << 7) + ar0 + mt * 16) * 33) + cb + akh) << 4);
                        ldsm4(a[mt], ad);
                    }
#pragma unroll
                    for (int ntp = 0; ntp < 4; ++ntp) {
                        mma16816(acc[0][ntp * 2],     a[0], bf[ntp][0], bf[ntp][1]);
                        mma16816(acc[0][ntp * 2 + 1], a[0], bf[ntp][2], bf[ntp][3]);
                        mma16816(acc[1][ntp * 2],     a[1], bf[ntp][0], bf[ntp][1]);
                        mma16816(acc[1][ntp * 2 + 1], a[1], bf[ntp][2], bf[ntp][3]);
                    }
                }
            }
            __syncthreads();    // all readers done with 'buf' before overwrite
        }

        // epilogue: mask diagonal, running argmax (j monotonic -> '>' keeps first)
#pragma unroll
        for (int mt = 0; mt < 2; ++mt)
#pragma unroll
            for (int nt = 0; nt < 8; ++nt)
#pragma unroll
                for (int rr = 0; rr < 4; ++rr) {
                    int jl = wn * 64 + nt * 8 + (lane & 3) * 2 + (rr & 1);
                    int il = wm * 32 + mt * 16 + (rr >> 1) * 8 + (lane >> 2);
                    float v = acc[mt][nt][rr];
                    if (j0 + jl == i0 + il) v = NEG;
                    int slot = mt * 2 + (rr >> 1);
                    if (v > best[slot]) { best[slot] = v; bidx[slot] = j0 + jl; }
                }
    }

    // cross-lane (quad) reduce, then merge the 4 wn-warps via smem
    float* Rv = (float*)(sm + MVOFF);   // [3][128]
    int*   Rj = (int*)(sm + MJOFF);
#pragma unroll
    for (int slot = 0; slot < 4; ++slot) {
        float v = best[slot]; int j = bidx[slot];
#pragma unroll
        for (int o = 1; o <= 2; o <<= 1) {
            float vo = __shfl_xor_sync(0xffffffffu, v, o);
            int   jo = __shfl_xor_sync(0xffffffffu, j, o);
            if (vo > v || (vo == v && jo < j)) { v = vo; j = jo; }
        }
        best[slot] = v; bidx[slot] = j;
        int row = wm * 32 + (slot >> 1) * 16 + (slot & 1) * 8 + (lane >> 2);
        if (wn > 0 && (lane & 3) == 0) {
            Rv[(wn - 1) * 128 + row] = v;
            Rj[(wn - 1) * 128 + row] = j;
        }
    }
    __syncthreads();
    if (wn == 0 && (lane & 3) == 0) {
#pragma unroll
        for (int slot = 0; slot < 4; ++slot) {
            int row = wm * 32 + (slot >> 1) * 16 + (slot & 1) * 8 + (lane >> 2);
            float v = best[slot]; int j = bidx[slot];
#pragma unroll
            for (int w = 0; w < 3; ++w) {
                float vo = Rv[w * 128 + row];
                int   jo = Rj[w * 128 + row];
                if (vo > v || (vo == v && jo < j)) { v = vo; j = jo; }
            }
            g_idx[b * NN + i0 + row] = j;
        }
    }
}

// ---------------------------------------------------------------------------
// fuse: staged in smem via g_xt; coalesced reads/writes. grid (NN/32, BB), 256 thr.
// ---------------------------------------------------------------------------
#define FS_SF 32896
#define FS_W  65792
#define FS_JI 69888
#define FS_W0 70016
#define FS_W1 70144
#define FS_TOTAL 70272

__global__ __launch_bounds__(256) void fuse_kernel(const float* __restrict__ W,
                                                   float* __restrict__ out) {
    extern __shared__ char fsm[];
    float* Sx  = (float*)fsm;               // [32][257]
    float* Sf  = (float*)(fsm + FS_SF);     // [32][257]
    float* Wsh = (float*)(fsm + FS_W);      // [1024]
    int*   Ji  = (int*)(fsm + FS_JI);
    float* W0  = (float*)(fsm + FS_W0);
    float* W1  = (float*)(fsm + FS_W1);

    int b = blockIdx.y, n0 = blockIdx.x * 32, tid = threadIdx.x;
    for (int e = tid; e < 1024; e += 256) Wsh[e] = W[e];
    if (tid < 32) Ji[tid] = g_idx[b * NN + n0 + tid];
    __syncthreads();

    const float* xtb = g_xt + (size_t)b * NN * 256;
    {
        int r = tid >> 3, p = tid & 7;
        const float* srcx = xtb + (size_t)(n0 + r) * 256 + p * 32;
        const float* srcf = xtb + (size_t)Ji[r] * 256 + p * 32;
#pragma unroll
        for (int q = 0; q < 8; ++q) {
            float4 a = *(const float4*)(srcx + q * 4);
            float4 c = *(const float4*)(srcf + q * 4);
            int cb = p * 32 + q * 4;
            Sx[r * 257 + cb] = a.x; Sx[r * 257 + cb + 1] = a.y;
            Sx[r * 257 + cb + 2] = a.z; Sx[r * 257 + cb + 3] = a.w;
            Sf[r * 257 + cb] = c.x; Sf[r * 257 + cb + 1] = c.y;
            Sf[r * 257 + cb + 2] = c.z; Sf[r * 257 + cb + 3] = c.w;
        }
    }
    __syncthreads();
    {
        int r = tid >> 3, p = tid & 7;
        float l0 = 0.f, l1 = 0.f;
#pragma unroll
        for (int cc = 0; cc < 32; ++cc) {
            int c = p * 32 + cc;
            float xv = Sx[r * 257 + c], fv = Sf[r * 257 + c];
            l0 = fmaf(xv, Wsh[c], fmaf(fv, Wsh[256 + c], l0));
            l1 = fmaf(xv, Wsh[512 + c], fmaf(fv, Wsh[768 + c], l1));
        }
#pragma unroll
        for (int o = 4; o; o >>= 1) {
            l0 += __shfl_down_sync(0xffffffffu, l0, o, 8);
            l1 += __shfl_down_sync(0xffffffffu, l1, o, 8);
        }
        if (p == 0) {
            float m = fmaxf(l0, l1);
            float e0 = expf(l0 - m), e1 = expf(l1 - m);
            float inv = 1.f / (e0 + e1);
            W0[r] = e0 * inv; W1[r] = e1 * inv;
        }
    }
    __syncthreads();
    {
        int nl = tid & 31, cg = tid >> 5;
        float w0 = W0[nl], w1 = W1[nl];
        float* o0 = out + (size_t)b * CC * NN;
        float* o1 = out + (size_t)BB * CC * NN + (size_t)b * CC * NN;
#pragma unroll
        for (int cc = 0; cc < 32; ++cc) {
            int c = cg * 32 + cc;
            float xv = Sx[nl * 257 + c], fv = Sf[nl * 257 + c];
            o0[(size_t)c * NN + n0 + nl] = fmaf(xv, w0, fv * w1);
            o1[(size_t)c * NN + n0 + nl] = fv;
        }
    }
}

// ---------------------------------------------------------------------------
extern "C" void kernel_launch(void* const* d_in, const int* in_sizes, int n_in,
                              void* d_out, int out_size) {
    const float* x = (const float*)d_in[0];
    const float* W = (const float*)d_in[1];
    float* out = (float*)d_out;

    cudaFuncSetAttribute(simargmax_kernel,
                         cudaFuncAttributeMaxDynamicSharedMemorySize, SMEM_TOTAL);
    cudaFuncSetAttribute(fuse_kernel,
                         cudaFuncAttributeMaxDynamicSharedMemorySize, FS_TOTAL);

    prep_kernel<<<dim3(NN / 32, BB), 256>>>(x);
    simargmax_kernel<<<dim3(16, BB), 512, SMEM_TOTAL>>>();
    fuse_kernel<<<dim3(NN / 32, BB), 256, FS_TOTAL>>>(W, out);
}